// round 16
// baseline (speedup 1.0000x reference)
#include <cuda_runtime.h>
#include <cuda_fp16.h>
#include <stdint.h>

#define N_NODES 50000
#define E_EDGES 500000
#define R_REL 8
#define HID 128
#define NRSEG (N_NODES * R_REL)
#define NG 64
#define EPS_BN 1e-5f

typedef unsigned long long ull;

// ------------------------- device scratch ------------------------------------
__device__ __align__(16) __half g_aggh[(size_t)NRSEG * 128];    // zero-init; empty segs stay 0
__device__ __align__(16) float g_raw[N_NODES * HID];
__device__ __align__(16) float g_emb[N_NODES * HID];
__device__ __align__(16) __half g_xh[N_NODES * HID];
__device__ __align__(16) __half g_hh[N_NODES * HID];
__device__ __align__(16) __half g_embh[N_NODES * HID];
__device__ __align__(16) __half g_gembh[NG * HID];
__device__ __align__(16) __half g_w1hi[128 * 1152];
__device__ __align__(16) __half g_w2hi[128 * 1152];
__device__ __align__(16) __half g_w3hi[128 * 1152];
__device__ __align__(16) __half g_c1hi[128 * 256], g_c1lo[128 * 256];
__device__ __align__(16) __half g_c2hi[128 * 128], g_c2lo[128 * 128];
__device__ __align__(16) __half g_a1thi[64 * 128], g_a1tlo[64 * 128];

__device__ int   g_src32[E_EDGES];
__device__ int   g_segid[E_EDGES];
__device__ int   g_srcsorted[E_EDGES];
__device__ int   g_hist[NRSEG];          // static zero-init; scan3 re-zeroes
__device__ int   g_segstart[NRSEG + 1];
__device__ int   g_cursor[NRSEG];
__device__ float g_inv[NRSEG];
__device__ int   g_batch32[N_NODES];
__device__ int   g_gstart[NG + 1];
__device__ float g_scores[N_NODES];
__device__ float g_colstats[4 * HID];    // [0:256) layer1, [256:512) layer2
__device__ float g_sumexp;
__device__ int   g_bsums[512];

// ------------------------- helpers ------------------------------------------
__device__ __forceinline__ float lrelu(float x) { return x > 0.f ? x : 0.1f * x; }

__device__ __forceinline__ uint32_t smem_u32(const void* p) {
    return (uint32_t)__cvta_generic_to_shared(p);
}
__device__ __forceinline__ uint32_t pk_h2(float a, float b) {
    __half2 h = __float22half2_rn(make_float2(a, b));
    return *(uint32_t*)&h;
}

// ------------------------- mma.sync / ldmatrix / cp.async --------------------
__device__ __forceinline__ void cp16(uint32_t dst, const void* src, uint32_t srcsz) {
    asm volatile("cp.async.ca.shared.global [%0], [%1], 16, %2;"
        :: "r"(dst), "l"(src), "r"(srcsz) : "memory");
}
__device__ __forceinline__ void cp_commit() {
    asm volatile("cp.async.commit_group;" ::: "memory");
}
template <int N>
__device__ __forceinline__ void cp_wait() {
    asm volatile("cp.async.wait_group %0;" :: "n"(N) : "memory");
}
__device__ __forceinline__ void ldm4(uint32_t* r, uint32_t addr) {
    asm volatile("ldmatrix.sync.aligned.m8n8.x4.shared.b16 {%0,%1,%2,%3}, [%4];"
        : "=r"(r[0]), "=r"(r[1]), "=r"(r[2]), "=r"(r[3]) : "r"(addr));
}
__device__ __forceinline__ void mma16816(float* c, const uint32_t* a, const uint32_t* b) {
    asm volatile("mma.sync.aligned.m16n8k16.row.col.f32.f16.f16.f32 "
        "{%0,%1,%2,%3}, {%4,%5,%6,%7}, {%8,%9}, {%0,%1,%2,%3};"
        : "+f"(c[0]), "+f"(c[1]), "+f"(c[2]), "+f"(c[3])
        : "r"(a[0]), "r"(a[1]), "r"(a[2]), "r"(a[3]), "r"(b[0]), "r"(b[1]));
}

// ------------------------- edge prep + x->fp16 (fused) -----------------------
__global__ void k_edge_prep(const void* __restrict__ ei, const void* __restrict__ et,
                            const void* __restrict__ bt, const float* __restrict__ x,
                            __half* __restrict__ xh) {
    __shared__ int s_is64;
    if (threadIdx.x < 32) {
        const ull* p = (const ull*)ei;
        ull m = 0;
#pragma unroll
        for (int i = 0; i < 8; i++) {
            ull v = p[threadIdx.x + i * 32];
            m = v > m ? v : m;
        }
        unsigned any64 = __ballot_sync(0xffffffffu, m >= (1ull << 32));
        if (threadIdx.x == 0) s_is64 = (any64 == 0u) ? 1 : 0;
    }
    __syncthreads();
    int is64 = s_is64;
    int e = blockIdx.x * blockDim.x + threadIdx.x;
    if (e < E_EDGES) {
        int src, dst, ty;
        if (is64) {
            const long long* p = (const long long*)ei;
            src = (int)p[e]; dst = (int)p[E_EDGES + e];
            ty = (int)((const long long*)et)[e];
        } else {
            const int* p = (const int*)ei;
            src = p[e]; dst = p[E_EDGES + e];
            ty = ((const int*)et)[e];
        }
        g_src32[e] = src;
        int s = dst * R_REL + ty;
        g_segid[e] = s;
        atomicAdd(&g_hist[s], 1);
    }
    if (e < N_NODES)
        g_batch32[e] = is64 ? (int)((const long long*)bt)[e] : ((const int*)bt)[e];
    if (e < N_NODES * 32) {
        float4 v = ((const float4*)x)[e];
        uint2 o;
        o.x = pk_h2(v.x, v.y);
        o.y = pk_h2(v.z, v.w);
        ((uint2*)xh)[e] = o;
    }
}

__global__ void k_scan1() {
    __shared__ int sd[256];
    int t = threadIdx.x;
    int base = blockIdx.x * 1024 + t * 4;
    int v0 = 0, v1 = 0, v2 = 0, v3 = 0;
    if (base + 0 < NRSEG) v0 = g_hist[base + 0];
    if (base + 1 < NRSEG) v1 = g_hist[base + 1];
    if (base + 2 < NRSEG) v2 = g_hist[base + 2];
    if (base + 3 < NRSEG) v3 = g_hist[base + 3];
    int ts = v0 + v1 + v2 + v3;
    sd[t] = ts; __syncthreads();
    for (int off = 1; off < 256; off <<= 1) {
        int x = (t >= off) ? sd[t - off] : 0;
        __syncthreads();
        sd[t] += x;
        __syncthreads();
    }
    int ex = sd[t] - ts;
    if (base + 0 < NRSEG) g_segstart[base + 0] = ex;
    ex += v0; if (base + 1 < NRSEG) g_segstart[base + 1] = ex;
    ex += v1; if (base + 2 < NRSEG) g_segstart[base + 2] = ex;
    ex += v2; if (base + 3 < NRSEG) g_segstart[base + 3] = ex;
    if (t == 255) g_bsums[blockIdx.x] = sd[255];
}

__global__ void k_scan2(int nb) {
    __shared__ int sd[512];
    int t = threadIdx.x;
    int v = (t < nb) ? g_bsums[t] : 0;
    sd[t] = v; __syncthreads();
    for (int off = 1; off < 512; off <<= 1) {
        int x = (t >= off) ? sd[t - off] : 0;
        __syncthreads();
        sd[t] += x;
        __syncthreads();
    }
    if (t < nb) g_bsums[t] = sd[t] - v;
}

__global__ void k_scan3() {
    int i = blockIdx.x * blockDim.x + threadIdx.x;
    if (i < NRSEG) {
        int v = g_segstart[i] + g_bsums[i >> 10];
        g_segstart[i] = v;
        g_cursor[i] = v;
        int c = g_hist[i];
        g_inv[i] = 1.0f / (float)(c > 0 ? c : 1);
        g_hist[i] = 0;            // self-clear for next graph replay
    }
    if (i < 4 * HID) g_colstats[i] = 0.f;
    if (i == 0) { g_segstart[NRSEG] = E_EDGES; g_sumexp = 0.f; }
}

__global__ void k_permute() {
    int e = blockIdx.x * blockDim.x + threadIdx.x;
    if (e < E_EDGES) {
        int s = g_segid[e];
        int pos = atomicAdd(&g_cursor[s], 1);
        g_srcsorted[pos] = g_src32[e];
    }
}

// ------------------------- aggregation (skip empty, src prefetch) ------------
__global__ void __launch_bounds__(256) k_aggregate(const __half* __restrict__ hsrc) {
    int warp = (blockIdx.x * blockDim.x + threadIdx.x) >> 5;
    int lane = threadIdx.x & 31;
    if (warp >= NRSEG) return;
    int beg = g_segstart[warp], end = g_segstart[warp + 1];
    if (beg == end) return;      // empty segment: aggh row stays zero forever
    float ax = 0.f, ay = 0.f, az = 0.f, aw = 0.f;
    int nxt = g_srcsorted[beg];
    for (int e = beg; e < end; e++) {
        int s = nxt;
        if (e + 1 < end) nxt = g_srcsorted[e + 1];   // prefetch: overlaps gather
        uint2 v = ((const uint2*)(hsrc + (size_t)s * 128))[lane];
        float2 f0 = __half22float2(*(__half2*)&v.x);
        float2 f1 = __half22float2(*(__half2*)&v.y);
        ax += f0.x; ay += f0.y; az += f1.x; aw += f1.y;
    }
    float inv = g_inv[warp];
    uint2 o;
    o.x = pk_h2(ax * inv, ay * inv);
    o.y = pk_h2(az * inv, aw * inv);
    ((uint2*)g_aggh)[(size_t)warp * 32 + lane] = o;
}

// ------------------------- weight prep ---------------------------------------
__global__ void k_wprep(const float* __restrict__ W, const float* __restrict__ root,
                        __half* __restrict__ bh) {
    int idx = blockIdx.x * blockDim.x + threadIdx.x;
    if (idx < 128 * 1152) {
        int c = idx / 1152, k = idx % 1152;
        float v = (k < 1024) ? W[((k >> 7) * 128 + (k & 127)) * 128 + c]
                             : root[(k - 1024) * 128 + c];
        bh[idx] = __float2half_rn(v);
    }
}

template <int K>
__global__ void k_cprep(const float* __restrict__ C, __half* __restrict__ bh,
                        __half* __restrict__ bl) {
    int idx = blockIdx.x * blockDim.x + threadIdx.x;
    if (idx < 128 * K) {
        int c = idx / K, k = idx % K;
        float v = C[k * 128 + c];
        __half h = __float2half_rn(v);
        bh[idx] = h;
        bl[idx] = __float2half_rn(v - __half2float(h));
    }
}

__global__ void k_a1prep(const float* __restrict__ A1) {
    int idx = blockIdx.x * blockDim.x + threadIdx.x;
    if (idx < 64 * 128) {
        int j = idx / 128, k = idx % 128;
        float v = A1[k * 64 + j];
        __half h = __float2half_rn(v);
        g_a1thi[idx] = h;
        g_a1tlo[idx] = __float2half_rn(v - __half2float(h));
    }
}

// ------------------------- mma.sync GEMM (128x128 tile, K-chunk 64) ----------
// 128x128 CTA tile, 256 thr, warp grid 4(M)x2(N), warp tile 32x64.
// MODE 0: +BN stats, out=raw. MODE 1: out=emb fp32 + embh.
// K-chunk 64, 3-stage cp.async pipeline; commit-count invariant maintained.
#define ROWB 80          // (combiner/scores) smem bytes per 32-col row
#define TILE_B 10240     // (combiner) 128 * 80
#define ROWB2 144        // layer GEMM: 64 fp16 + 16B pad
#define TILE2 18432      // 128 * 144
#define CP 132           // staging row stride (floats)

template <int MODE, int KT>
__global__ void __launch_bounds__(256, 2) k_mgemm(
    const __half* __restrict__ A, const __half* __restrict__ A2,
    const __half* __restrict__ Bhi,
    const float* __restrict__ bias,
    float* __restrict__ outf, __half* __restrict__ oh,
    float* __restrict__ statsf) {
    constexpr int NCH = KT / 64;        // 18
    constexpr int STAGES = 3;
    constexpr int SBUF = 2 * TILE2;     // A + B per stage
    extern __shared__ __align__(16) char dsm[];
    __shared__ float s_bias[128];

    int tid = threadIdx.x;
    int bm = blockIdx.x * 128;
    int wid = tid >> 5, lane = tid & 31;
    int mo = (wid & 3) * 32;
    int no = (wid >> 2) * 64;
    uint32_t sbase = smem_u32(dsm);

    if (tid < 128) s_bias[tid] = bias[tid];

    float acc[2][8][4];
#pragma unroll
    for (int mi = 0; mi < 2; mi++)
#pragma unroll
        for (int j = 0; j < 8; j++)
#pragma unroll
            for (int q = 0; q < 4; q++) acc[mi][j][q] = 0.f;

    auto loadChunk = [&](int i) {
        int st = i % STAGES;
        uint32_t sb = sbase + (uint32_t)(st * SBUF);
        int k0 = i * 64;
#pragma unroll
        for (int it = 0; it < 4; it++) {
            int idx = it * 256 + tid;          // 0..1023
            int row = idx >> 3, seg = idx & 7; // 8 x 16B = 128B per row
            int n = bm + row;
            bool v = (n < N_NODES);
            int nn = v ? n : 0;
            const __half* pa = (k0 < 1024) ? A + (size_t)nn * 1024 + k0
                                           : A2 + (size_t)nn * 128 + (k0 - 1024);
            cp16(sb + (uint32_t)(row * ROWB2 + seg * 16), pa + seg * 8, v ? 16u : 0u);
            uint32_t db = sb + TILE2 + (uint32_t)(row * ROWB2 + seg * 16);
            cp16(db, Bhi + (size_t)row * KT + k0 + seg * 8, 16u);
        }
        cp_commit();
    };

    loadChunk(0);
    loadChunk(1);
    for (int i = 0; i < NCH; i++) {
        cp_wait<1>();
        __syncthreads();
        if (i + 2 < NCH) loadChunk(i + 2);
        else cp_commit();   // empty group: keeps commit-count invariant
        uint32_t ab = sbase + (uint32_t)((i % STAGES) * SBUF);
#pragma unroll
        for (int kk = 0; kk < 4; kk++) {
            uint32_t a[2][4];
#pragma unroll
            for (int mi = 0; mi < 2; mi++) {
                uint32_t r = (uint32_t)(mo + mi * 16 + (lane & 15));
                uint32_t c = (uint32_t)(kk * 16 + (lane >> 4) * 8);
                ldm4(a[mi], ab + r * ROWB2 + c * 2);
            }
#pragma unroll
            for (int jp = 0; jp < 4; jp++) {
                uint32_t r = (uint32_t)(no + jp * 16 + (lane & 15));
                uint32_t c = (uint32_t)(kk * 16 + (lane >> 4) * 8);
                uint32_t t[4];
                ldm4(t, ab + TILE2 + r * ROWB2 + c * 2);
                uint32_t bh0[2] = {t[0], t[2]}, bh1[2] = {t[1], t[3]};
#pragma unroll
                for (int mi = 0; mi < 2; mi++) {
                    mma16816(acc[mi][jp * 2 + 0], a[mi], bh0);
                    mma16816(acc[mi][jp * 2 + 1], a[mi], bh1);
                }
            }
        }
    }
    cp_wait<0>();      // drain all (incl. empty) groups before smem reuse
    __syncthreads();

    // ---- stage accumulators to smem (128 x 128) ----
    float* Cs = (float*)dsm;
#pragma unroll
    for (int mi = 0; mi < 2; mi++)
#pragma unroll
        for (int j = 0; j < 8; j++) {
            int r0 = mo + mi * 16 + (lane >> 2);
            int col = no + j * 8 + (lane & 3) * 2;
            *(float2*)&Cs[r0 * CP + col] = make_float2(acc[mi][j][0], acc[mi][j][1]);
            *(float2*)&Cs[(r0 + 8) * CP + col] = make_float2(acc[mi][j][2], acc[mi][j][3]);
        }
    __syncthreads();

    // ---- BN column stats: thread owns (col, half), serial 64-row sum --------
    if (MODE == 0) {
        int col = tid & 127, half = tid >> 7;
        float b = s_bias[col];
        int r0 = half * 64;
        float s = 0.f, q = 0.f;
        int nvalid = N_NODES - bm - r0;
        int rmax = nvalid < 64 ? (nvalid < 0 ? 0 : nvalid) : 64;
        for (int r = 0; r < rmax; r++) {
            float v = Cs[(r0 + r) * CP + col] + b;
            s += v; q += v * v;
        }
        atomicAdd(&statsf[col], s);
        atomicAdd(&statsf[128 + col], q);
    }

    // ---- per-row epilogue: threads 0..127 own row tid ----
    if (tid < 128) {
        int n = bm + tid;
        bool valid = (n < N_NODES);
        const float* crow = &Cs[tid * CP];
        if (valid) {
#pragma unroll
            for (int cb = 0; cb < 4; cb++) {
                float vf[32];
#pragma unroll
                for (int j = 0; j < 32; j++)
                    vf[j] = crow[cb * 32 + j] + s_bias[cb * 32 + j];
#pragma unroll
                for (int j4 = 0; j4 < 8; j4++)
                    *(float4*)&outf[(size_t)n * 128 + cb * 32 + j4 * 4] =
                        make_float4(vf[j4 * 4], vf[j4 * 4 + 1], vf[j4 * 4 + 2], vf[j4 * 4 + 3]);
                if (MODE == 1) {
                    uint32_t* ph = (uint32_t*)(oh + (size_t)n * 128 + cb * 32);
#pragma unroll
                    for (int j2 = 0; j2 < 16; j2++)
                        ph[j2] = pk_h2(vf[j2 * 2], vf[j2 * 2 + 1]);
                }
            }
        }
    }
}

// ------------------------- fused combiner MLP ---------------------------------
// Phase 1: t1 = lrelu([embh|gembh[batch]] @ C1^T + c1)  (K=256, C1 split)
// Phase 2: out = rownorm(t1 @ C2^T + c2)                (K=128, C2 split)
#define T1_OFF 67584                // after Cs staging region (128*132*4)
#define DSMC (T1_OFF + 4 * TILE_B)  // 108544

__global__ void __launch_bounds__(256) k_comb(
    const int* __restrict__ batch,
    const float* __restrict__ c1bias, const float* __restrict__ c2bias,
    float* __restrict__ outf) {
    extern __shared__ __align__(16) char dsm[];
    __shared__ float s_b1[128], s_b2[128];

    int tid = threadIdx.x;
    int bm = blockIdx.x * 128;
    int wid = tid >> 5, lane = tid & 31;
    int mo = (wid & 3) * 32;
    int no = (wid >> 2) * 64;
    uint32_t sbase = smem_u32(dsm);
    float* Cs = (float*)dsm;

    if (tid < 128) { s_b1[tid] = c1bias[tid]; s_b2[tid] = c2bias[tid]; }

    float acc[2][8][4];
#pragma unroll
    for (int mi = 0; mi < 2; mi++)
#pragma unroll
        for (int j = 0; j < 8; j++)
#pragma unroll
            for (int q = 0; q < 4; q++) acc[mi][j][q] = 0.f;

    auto load1 = [&](int i) {
        uint32_t sb = sbase + (uint32_t)((i & 1) * (3 * TILE_B));
        int k0 = i * 32;
#pragma unroll
        for (int it = 0; it < 2; it++) {
            int idx = it * 256 + tid;
            int row = idx >> 2, seg = idx & 3;
            int n = bm + row;
            bool v = (n < N_NODES);
            int nn = v ? n : 0;
            const __half* pa;
            if (k0 < 128) pa = g_embh + (size_t)nn * 128 + k0;
            else {
                int g = v ? batch[nn] : 0;
                pa = g_gembh + (size_t)g * 128 + (k0 - 128);
            }
            cp16(sb + (uint32_t)(row * ROWB + seg * 16), pa + seg * 8, v ? 16u : 0u);
            uint32_t db = sb + TILE_B + (uint32_t)(row * ROWB + seg * 16);
            cp16(db, g_c1hi + (size_t)row * 256 + k0 + seg * 8, 16u);
            cp16(db + TILE_B, g_c1lo + (size_t)row * 256 + k0 + seg * 8, 16u);
        }
        cp_commit();
    };

    load1(0);
    for (int i = 0; i < 8; i++) {
        cp_wait<0>();
        __syncthreads();
        if (i + 1 < 8) load1(i + 1);
        else cp_commit();
        uint32_t ab = sbase + (uint32_t)((i & 1) * (3 * TILE_B));
#pragma unroll
        for (int kk = 0; kk < 2; kk++) {
            uint32_t a[2][4];
#pragma unroll
            for (int mi = 0; mi < 2; mi++) {
                uint32_t r = (uint32_t)(mo + mi * 16 + (lane & 15));
                uint32_t c = (uint32_t)(kk * 16 + (lane >> 4) * 8);
                ldm4(a[mi], ab + r * ROWB + c * 2);
            }
#pragma unroll
            for (int jp = 0; jp < 4; jp++) {
                uint32_t r = (uint32_t)(no + jp * 16 + (lane & 15));
                uint32_t c = (uint32_t)(kk * 16 + (lane >> 4) * 8);
                uint32_t bd = ab + TILE_B + r * ROWB + c * 2;
                uint32_t t[4], u[4];
                ldm4(t, bd);
                ldm4(u, bd + TILE_B);
                uint32_t bh0[2] = {t[0], t[2]}, bh1[2] = {t[1], t[3]};
                uint32_t bl0[2] = {u[0], u[2]}, bl1[2] = {u[1], u[3]};
#pragma unroll
                for (int mi = 0; mi < 2; mi++) {
                    mma16816(acc[mi][jp * 2 + 0], a[mi], bh0);
                    mma16816(acc[mi][jp * 2 + 0], a[mi], bl0);
                    mma16816(acc[mi][jp * 2 + 1], a[mi], bh1);
                    mma16816(acc[mi][jp * 2 + 1], a[mi], bl1);
                }
            }
        }
    }
    cp_wait<0>();
    __syncthreads();

#pragma unroll
    for (int mi = 0; mi < 2; mi++)
#pragma unroll
        for (int j = 0; j < 8; j++) {
            int r0 = mo + mi * 16 + (lane >> 2);
            int col = no + j * 8 + (lane & 3) * 2;
            *(float2*)&Cs[r0 * CP + col] = make_float2(acc[mi][j][0], acc[mi][j][1]);
            *(float2*)&Cs[(r0 + 8) * CP + col] = make_float2(acc[mi][j][2], acc[mi][j][3]);
        }
    __syncthreads();

    if (tid < 128) {
        const float* crow = &Cs[tid * CP];
#pragma unroll
        for (int cb = 0; cb < 4; cb++) {
            uint32_t* pt = (uint32_t*)(dsm + T1_OFF + cb * TILE_B + tid * ROWB);
#pragma unroll
            for (int j2 = 0; j2 < 16; j2++) {
                float v0 = lrelu(crow[cb * 32 + j2 * 2 + 0] + s_b1[cb * 32 + j2 * 2 + 0]);
                float v1 = lrelu(crow[cb * 32 + j2 * 2 + 1] + s_b1[cb * 32 + j2 * 2 + 1]);
                pt[j2] = pk_h2(v0, v1);
            }
        }
    }
    __syncthreads();

#pragma unroll
    for (int mi = 0; mi < 2; mi++)
#pragma unroll
        for (int j = 0; j < 8; j++)
#pragma unroll
            for (int q = 0; q < 4; q++) acc[mi][j][q] = 0.f;

    auto load2 = [&](int i) {
        uint32_t sb = sbase + (uint32_t)((i & 1) * (2 * TILE_B));
        int k0 = i * 32;
#pragma unroll
        for (int it = 0; it < 2; it++) {
            int idx = it * 256 + tid;
            int row = idx >> 2, seg = idx & 3;
            cp16(sb + (uint32_t)(row * ROWB + seg * 16),
                 g_c2hi + (size_t)row * 128 + k0 + seg * 8, 16u);
            cp16(sb + TILE_B + (uint32_t)(row * ROWB + seg * 16),
                 g_c2lo + (size_t)row * 128 + k0 + seg * 8, 16u);
        }
        cp_commit();
    };

    load2(0);
    for (int i = 0; i < 4; i++) {
        cp_wait<0>();
        __syncthreads();
        if (i + 1 < 4) load2(i + 1);
        else cp_commit();
        uint32_t ab = sbase + (uint32_t)((i & 1) * (2 * TILE_B));
        uint32_t at = sbase + (uint32_t)(T1_OFF + i * TILE_B);
#pragma unroll
        for (int kk = 0; kk < 2; kk++) {
            uint32_t a[2][4];
#pragma unroll
            for (int mi = 0; mi < 2; mi++) {
                uint32_t r = (uint32_t)(mo + mi * 16 + (lane & 15));
                uint32_t c = (uint32_t)(kk * 16 + (lane >> 4) * 8);
                ldm4(a[mi], at + r * ROWB + c * 2);
            }
#pragma unroll
            for (int jp = 0; jp < 4; jp++) {
                uint32_t r = (uint32_t)(no + jp * 16 + (lane & 15));
                uint32_t c = (uint32_t)(kk * 16 + (lane >> 4) * 8);
                uint32_t bd = ab + r * ROWB + c * 2;
                uint32_t t[4], u[4];
                ldm4(t, bd);
                ldm4(u, bd + TILE_B);
                uint32_t bh0[2] = {t[0], t[2]}, bh1[2] = {t[1], t[3]};
                uint32_t bl0[2] = {u[0], u[2]}, bl1[2] = {u[1], u[3]};
#pragma unroll
                for (int mi = 0; mi < 2; mi++) {
                    mma16816(acc[mi][jp * 2 + 0], a[mi], bh0);
                    mma16816(acc[mi][jp * 2 + 0], a[mi], bl0);
                    mma16816(acc[mi][jp * 2 + 1], a[mi], bh1);
                    mma16816(acc[mi][jp * 2 + 1], a[mi], bl1);
                }
            }
        }
    }
    cp_wait<0>();
    __syncthreads();

#pragma unroll
    for (int mi = 0; mi < 2; mi++)
#pragma unroll
        for (int j = 0; j < 8; j++) {
            int r0 = mo + mi * 16 + (lane >> 2);
            int col = no + j * 8 + (lane & 3) * 2;
            *(float2*)&Cs[r0 * CP + col] = make_float2(acc[mi][j][0], acc[mi][j][1]);
            *(float2*)&Cs[(r0 + 8) * CP + col] = make_float2(acc[mi][j][2], acc[mi][j][3]);
        }
    __syncthreads();

    if (tid < 128) {
        int n = bm + tid;
        bool valid = (n < N_NODES);
        const float* crow = &Cs[tid * CP];
        float ss = 0.f;
#pragma unroll 8
        for (int c = 0; c < 128; c++) {
            float v = crow[c] + s_b2[c];
            ss += v * v;
        }
        float sc = 1.f / fmaxf(sqrtf(ss), 1e-12f);
        if (valid) {
#pragma unroll
            for (int c4 = 0; c4 < 32; c4++) {
                float4 o;
                o.x = (crow[c4 * 4 + 0] + s_b2[c4 * 4 + 0]) * sc;
                o.y = (crow[c4 * 4 + 1] + s_b2[c4 * 4 + 1]) * sc;
                o.z = (crow[c4 * 4 + 2] + s_b2[c4 * 4 + 2]) * sc;
                o.w = (crow[c4 * 4 + 3] + s_b2[c4 * 4 + 3]) * sc;
                *(float4*)&outf[(size_t)n * 128 + c4 * 4] = o;
            }
        }
    }
}

// ------------------------- BN apply (self-computing scale/shift) --------------
__global__ void k_bnapply(const float* __restrict__ gamma, const float* __restrict__ beta,
                          const float* __restrict__ stats) {
    __shared__ float s_sc[128], s_sh[128];
    if (threadIdx.x < 128) {
        int c = threadIdx.x;
        float inv_n = 1.f / (float)N_NODES;
        float mu = stats[c] * inv_n;
        float var = fmaxf(stats[128 + c] * inv_n - mu * mu, 0.f);
        float sc = gamma[c] * rsqrtf(var + EPS_BN);
        s_sc[c] = sc;
        s_sh[c] = beta[c] - mu * sc;
    }
    __syncthreads();
    int i = blockIdx.x * blockDim.x + threadIdx.x;
    if (i < N_NODES * 32) {
        float4 v = ((const float4*)g_raw)[i];
        int c4 = i & 31;
        float4 sc = *(const float4*)&s_sc[c4 * 4];
        float4 sh = *(const float4*)&s_sh[c4 * 4];
        float ox = lrelu(v.x * sc.x + sh.x);
        float oy = lrelu(v.y * sc.y + sh.y);
        float oz = lrelu(v.z * sc.z + sh.z);
        float ow = lrelu(v.w * sc.w + sh.w);
        uint2 o;
        o.x = pk_h2(ox, oy);
        o.y = pk_h2(oz, ow);
        ((uint2*)g_hh)[i] = o;
    }
}

// ------------------------- attention scores (tensor cores + fused sumexp) -----
#define SROWB 272
#define SAT 34816
#define SBT 17408
#define SCP 68

__global__ void __launch_bounds__(256, 2) k_scoresT(
    const float* __restrict__ a1, const float* __restrict__ A2v,
    const float* __restrict__ a2v) {
    extern __shared__ __align__(16) char dsm[];
    __shared__ float s_a1[64];
    __shared__ float s_A2[64];
    __shared__ float s_esum;
    int tid = threadIdx.x;
    int bm = blockIdx.x * 128;
    int wid = tid >> 5, lane = tid & 31;
    int mo = (wid & 3) * 32;
    int no = (wid >> 2) * 32;
    uint32_t sbase = smem_u32(dsm);

    if (tid < 64) { s_a1[tid] = a1[tid]; s_A2[tid] = A2v[tid]; }
    if (tid == 0) s_esum = 0.f;

#pragma unroll
    for (int it = 0; it < 8; it++) {
        int idx = it * 256 + tid;
        int row = idx >> 4, seg = idx & 15;
        int n = bm + row;
        bool v = (n < N_NODES);
        cp16(sbase + (uint32_t)(row * SROWB + seg * 16),
             g_embh + (size_t)(v ? n : 0) * 128 + seg * 8, v ? 16u : 0u);
    }
#pragma unroll
    for (int it = 0; it < 4; it++) {
        int idx = it * 256 + tid;
        int row = idx >> 4, seg = idx & 15;
        uint32_t db = sbase + SAT + (uint32_t)(row * SROWB + seg * 16);
        cp16(db, g_a1thi + (size_t)row * 128 + seg * 8, 16u);
        cp16(db + SBT, g_a1tlo + (size_t)row * 128 + seg * 8, 16u);
    }
    cp_commit();
    cp_wait<0>();
    __syncthreads();

    float acc[2][4][4];
#pragma unroll
    for (int mi = 0; mi < 2; mi++)
#pragma unroll
        for (int j = 0; j < 4; j++)
#pragma unroll
            for (int q = 0; q < 4; q++) acc[mi][j][q] = 0.f;

#pragma unroll
    for (int kk = 0; kk < 8; kk++) {
        uint32_t a[2][4];
#pragma unroll
        for (int mi = 0; mi < 2; mi++) {
            uint32_t r = (uint32_t)(mo + mi * 16 + (lane & 15));
            uint32_t c = (uint32_t)(kk * 16 + (lane >> 4) * 8);
            ldm4(a[mi], sbase + r * SROWB + c * 2);
        }
#pragma unroll
        for (int jn = 0; jn < 2; jn++) {
            uint32_t r = (uint32_t)(no + jn * 16 + (lane & 15));
            uint32_t c = (uint32_t)(kk * 16 + (lane >> 4) * 8);
            uint32_t bd = sbase + SAT + r * SROWB + c * 2;
            uint32_t t[4], u[4];
            ldm4(t, bd);
            ldm4(u, bd + SBT);
            uint32_t bh0[2] = {t[0], t[2]}, bh1[2] = {t[1], t[3]};
            uint32_t bl0[2] = {u[0], u[2]}, bl1[2] = {u[1], u[3]};
#pragma unroll
            for (int mi = 0; mi < 2; mi++) {
                mma16816(acc[mi][jn * 2 + 0], a[mi], bh0);
                mma16816(acc[mi][jn * 2 + 0], a[mi], bl0);
                mma16816(acc[mi][jn * 2 + 1], a[mi], bh1);
                mma16816(acc[mi][jn * 2 + 1], a[mi], bl1);
            }
        }
    }
    __syncthreads();

    float* Cs = (float*)dsm;
#pragma unroll
    for (int mi = 0; mi < 2; mi++)
#pragma unroll
        for (int j = 0; j < 4; j++) {
            int r0 = mo + mi * 16 + (lane >> 2);
            int col = no + j * 8 + (lane & 3) * 2;
            *(float2*)&Cs[r0 * SCP + col] = make_float2(acc[mi][j][0], acc[mi][j][1]);
            *(float2*)&Cs[(r0 + 8) * SCP + col] = make_float2(acc[mi][j][2], acc[mi][j][3]);
        }
    __syncthreads();

    if (tid < 128) {
        int n = bm + tid;
        bool valid = (n < N_NODES);
        const float* crow = &Cs[tid * SCP];
        float s = 0.f;
#pragma unroll 8
        for (int j = 0; j < 64; j++)
            s += lrelu(crow[j] + s_a1[j]) * s_A2[j];
        float score = s + a2v[0];
        if (valid) g_scores[n] = score;
        float ex = valid ? expf(score) : 0.f;
#pragma unroll
        for (int off = 16; off > 0; off >>= 1)
            ex += __shfl_xor_sync(0xffffffffu, ex, off);
        if ((tid & 31) == 0) atomicAdd(&s_esum, ex);
    }
    __syncthreads();
    if (tid == 0) atomicAdd(&g_sumexp, s_esum);
}

__global__ void k_gbounds() {
    int i = blockIdx.x * blockDim.x + threadIdx.x;
    if (i <= N_NODES) {
        int cur = (i < N_NODES) ? g_batch32[i] : NG;
        int prev = (i == 0) ? -1 : g_batch32[i - 1];
        for (int g = prev + 1; g <= cur && g <= NG; g++) g_gstart[g] = i;
    }
}

// pool: 1024 thr = 32 node-lanes x 32 col-threads
__global__ void __launch_bounds__(1024) k_pool() {
    __shared__ float s_red[32][128];
    int g = blockIdx.x;
    int ty = threadIdx.x >> 5, tx = threadIdx.x & 31;
    float invs = 1.f / g_sumexp;
    int b = g_gstart[g], e = g_gstart[g + 1];
    float4 acc = make_float4(0.f, 0.f, 0.f, 0.f);
    for (int n = b + ty; n < e; n += 32) {
        float w = expf(g_scores[n]) * invs;
        float4 v = *(const float4*)&g_emb[(size_t)n * 128 + tx * 4];
        acc.x += v.x * w; acc.y += v.y * w; acc.z += v.z * w; acc.w += v.w * w;
    }
    *(float4*)&s_red[ty][tx * 4] = acc;
    __syncthreads();
    if (threadIdx.x < 128) {
        int c = threadIdx.x;
        float s = 0.f;
#pragma unroll
        for (int t = 0; t < 32; t++) s += s_red[t][c];
        g_gembh[g * 128 + c] = __float2half_rn(s);
    }
}

// ------------------------- host launcher --------------------------------------
extern "C" void kernel_launch(void* const* d_in, const int* in_sizes, int n_in,
                              void* d_out, int out_size) {
    const float* x     = (const float*)d_in[0];
    const void*  ei    = d_in[1];
    const void*  et    = d_in[2];
    const void*  bt    = d_in[3];
    const float* W1    = (const float*)d_in[4];
    const float* root1 = (const float*)d_in[5];
    const float* b1    = (const float*)d_in[6];
    const float* W2    = (const float*)d_in[7];
    const float* root2 = (const float*)d_in[8];
    const float* b2    = (const float*)d_in[9];
    const float* W3    = (const float*)d_in[10];
    const float* root3 = (const float*)d_in[11];
    const float* b3    = (const float*)d_in[12];
    const float* g1    = (const float*)d_in[13];
    const float* beta1 = (const float*)d_in[14];
    const float* g2    = (const float*)d_in[15];
    const float* beta2 = (const float*)d_in[16];
    const float* A1    = (const float*)d_in[17];
    const float* a1    = (const float*)d_in[18];
    const float* A2    = (const float*)d_in[19];
    const float* a2    = (const float*)d_in[20];
    const float* C1    = (const float*)d_in[21];
    const float* c1    = (const float*)d_in[22];
    const float* C2    = (const float*)d_in[23];
    const float* c2    = (const float*)d_in[24];
    float* out = (float*)d_out;

    void* p;
    cudaGetSymbolAddress(&p, g_aggh);   __half* aggh = (__half*)p;
    cudaGetSymbolAddress(&p, g_raw);    float* raw  = (float*)p;
    cudaGetSymbolAddress(&p, g_emb);    float* emb  = (float*)p;
    cudaGetSymbolAddress(&p, g_xh);     __half* xh = (__half*)p;
    cudaGetSymbolAddress(&p, g_hh);     __half* hh = (__half*)p;
    cudaGetSymbolAddress(&p, g_embh);   __half* embh = (__half*)p;
    cudaGetSymbolAddress(&p, g_w1hi);   __half* w1hi = (__half*)p;
    cudaGetSymbolAddress(&p, g_w2hi);   __half* w2hi = (__half*)p;
    cudaGetSymbolAddress(&p, g_w3hi);   __half* w3hi = (__half*)p;
    cudaGetSymbolAddress(&p, g_c1hi);   __half* c1hi = (__half*)p;
    cudaGetSymbolAddress(&p, g_c1lo);   __half* c1lo = (__half*)p;
    cudaGetSymbolAddress(&p, g_c2hi);   __half* c2hi = (__half*)p;
    cudaGetSymbolAddress(&p, g_c2lo);   __half* c2lo = (__half*)p;
    cudaGetSymbolAddress(&p, g_batch32); int* batch32 = (int*)p;
    cudaGetSymbolAddress(&p, g_colstats); float* colstats = (float*)p;

    const int DSM0 = 3 * 2 * TILE2;             // 110592 (layer GEMMs, 3 stages)
    const int DSMS = SAT + 2 * SBT;             // 69632 (scores)
    cudaFuncSetAttribute(k_mgemm<0, 1152>, cudaFuncAttributeMaxDynamicSharedMemorySize, DSM0);
    cudaFuncSetAttribute(k_mgemm<1, 1152>, cudaFuncAttributeMaxDynamicSharedMemorySize, DSM0);
    cudaFuncSetAttribute(k_comb, cudaFuncAttributeMaxDynamicSharedMemorySize, DSMC);
    cudaFuncSetAttribute(k_scoresT, cudaFuncAttributeMaxDynamicSharedMemorySize, DSMS);

    const int NB1 = (NRSEG + 1023) / 1024;
    const int GB128 = (N_NODES + 127) / 128;  // 391
    const int AGG_BLOCKS = NRSEG / 8;         // 50000

    // prep chain
    k_edge_prep<<<(N_NODES * 32 + 255) / 256, 256>>>(ei, et, bt, x, xh);
    k_scan1<<<NB1, 256>>>();
    k_scan2<<<1, 512>>>(NB1);
    k_scan3<<<(NRSEG + 255) / 256, 256>>>();
    k_permute<<<(E_EDGES + 255) / 256, 256>>>();
    k_aggregate<<<AGG_BLOCKS, 256>>>(xh);

    k_wprep<<<(128 * 1152 + 255) / 256, 256>>>(W1, root1, w1hi);
    k_wprep<<<(128 * 1152 + 255) / 256, 256>>>(W2, root2, w2hi);
    k_wprep<<<(128 * 1152 + 255) / 256, 256>>>(W3, root3, w3hi);
    k_cprep<256><<<(128 * 256 + 255) / 256, 256>>>(C1, c1hi, c1lo);
    k_cprep<128><<<(128 * 128 + 255) / 256, 256>>>(C2, c2hi, c2lo);
    k_a1prep<<<(64 * 128 + 255) / 256, 256>>>(A1);
    k_gbounds<<<(N_NODES + 256) / 256, 256>>>();

    // layer 1 (stats -> colstats[0:256))
    k_mgemm<0, 1152><<<GB128, 256, DSM0>>>(aggh, xh, w1hi, b1, raw, nullptr, colstats);
    k_bnapply<<<(N_NODES * 32 + 255) / 256, 256>>>(g1, beta1, colstats);

    // layer 2 (stats -> colstats[256:512))
    k_aggregate<<<AGG_BLOCKS, 256>>>(hh);
    k_mgemm<0, 1152><<<GB128, 256, DSM0>>>(aggh, hh, w2hi, b2, raw, nullptr, colstats + 256);
    k_bnapply<<<(N_NODES * 32 + 255) / 256, 256>>>(g2, beta2, colstats + 256);

    // layer 3
    k_aggregate<<<AGG_BLOCKS, 256>>>(hh);
    k_mgemm<1, 1152><<<GB128, 256, DSM0>>>(aggh, hh, w3hi, b3, emb, embh, nullptr);

    // attention pooling (sumexp fused into scores; softmax max-shift cancels)
    k_scoresT<<<GB128, 256, DSMS>>>(a1, A2, a2);
    k_pool<<<NG, 1024>>>();

    // fused combiner MLP + row normalize
    k_comb<<<GB128, 256, DSMC>>>(batch32, c1, c2, out);

    (void)in_sizes; (void)n_in; (void)out_size;
}

// round 17
// speedup vs baseline: 1.0829x; 1.0829x over previous
#include <cuda_runtime.h>
#include <cuda_fp16.h>
#include <stdint.h>

#define N_NODES 50000
#define E_EDGES 500000
#define R_REL 8
#define HID 128
#define NRSEG (N_NODES * R_REL)
#define NG 64
#define EPS_BN 1e-5f

typedef unsigned long long ull;

// ------------------------- device scratch ------------------------------------
__device__ __align__(16) __half g_aggh[(size_t)NRSEG * 128];    // zero-init; empty segs stay 0
__device__ __align__(16) float g_raw[N_NODES * HID];
__device__ __align__(16) float g_emb[N_NODES * HID];
__device__ __align__(16) __half g_xh[N_NODES * HID];
__device__ __align__(16) __half g_hh[N_NODES * HID];
__device__ __align__(16) __half g_embh[N_NODES * HID];
__device__ __align__(16) __half g_gembh[NG * HID];
__device__ __align__(16) __half g_w1hi[128 * 1152];
__device__ __align__(16) __half g_w2hi[128 * 1152];
__device__ __align__(16) __half g_w3hi[128 * 1152];
__device__ __align__(16) __half g_c1hi[128 * 256], g_c1lo[128 * 256];
__device__ __align__(16) __half g_c2hi[128 * 128], g_c2lo[128 * 128];
__device__ __align__(16) __half g_a1thi[64 * 128], g_a1tlo[64 * 128];

__device__ int   g_src32[E_EDGES];
__device__ int   g_segid[E_EDGES];
__device__ int   g_srcsorted[E_EDGES];
__device__ int   g_hist[NRSEG];          // static zero-init; scan3 re-zeroes
__device__ int   g_segstart[NRSEG + 1];
__device__ int   g_cursor[NRSEG];
__device__ float g_inv[NRSEG];
__device__ int   g_batch32[N_NODES];
__device__ int   g_gstart[NG + 1];
__device__ float g_scores[N_NODES];
__device__ float g_colstats[4 * HID];    // [0:256) layer1, [256:512) layer2
__device__ float g_sumexp;
__device__ int   g_bsums[512];

// ------------------------- helpers ------------------------------------------
__device__ __forceinline__ float lrelu(float x) { return x > 0.f ? x : 0.1f * x; }

__device__ __forceinline__ uint32_t smem_u32(const void* p) {
    return (uint32_t)__cvta_generic_to_shared(p);
}
__device__ __forceinline__ uint32_t pk_h2(float a, float b) {
    __half2 h = __float22half2_rn(make_float2(a, b));
    return *(uint32_t*)&h;
}

// ------------------------- mma.sync / ldmatrix / cp.async --------------------
__device__ __forceinline__ void cp16(uint32_t dst, const void* src, uint32_t srcsz) {
    asm volatile("cp.async.ca.shared.global [%0], [%1], 16, %2;"
        :: "r"(dst), "l"(src), "r"(srcsz) : "memory");
}
__device__ __forceinline__ void cp_commit() {
    asm volatile("cp.async.commit_group;" ::: "memory");
}
template <int N>
__device__ __forceinline__ void cp_wait() {
    asm volatile("cp.async.wait_group %0;" :: "n"(N) : "memory");
}
__device__ __forceinline__ void ldm4(uint32_t* r, uint32_t addr) {
    asm volatile("ldmatrix.sync.aligned.m8n8.x4.shared.b16 {%0,%1,%2,%3}, [%4];"
        : "=r"(r[0]), "=r"(r[1]), "=r"(r[2]), "=r"(r[3]) : "r"(addr));
}
__device__ __forceinline__ void mma16816(float* c, const uint32_t* a, const uint32_t* b) {
    asm volatile("mma.sync.aligned.m16n8k16.row.col.f32.f16.f16.f32 "
        "{%0,%1,%2,%3}, {%4,%5,%6,%7}, {%8,%9}, {%0,%1,%2,%3};"
        : "+f"(c[0]), "+f"(c[1]), "+f"(c[2]), "+f"(c[3])
        : "r"(a[0]), "r"(a[1]), "r"(a[2]), "r"(a[3]), "r"(b[0]), "r"(b[1]));
}

// ------------------------- edge prep + x->fp16 (fused) -----------------------
__global__ void k_edge_prep(const void* __restrict__ ei, const void* __restrict__ et,
                            const void* __restrict__ bt, const float* __restrict__ x,
                            __half* __restrict__ xh) {
    __shared__ int s_is64;
    if (threadIdx.x < 32) {
        const ull* p = (const ull*)ei;
        ull m = 0;
#pragma unroll
        for (int i = 0; i < 8; i++) {
            ull v = p[threadIdx.x + i * 32];
            m = v > m ? v : m;
        }
        unsigned any64 = __ballot_sync(0xffffffffu, m >= (1ull << 32));
        if (threadIdx.x == 0) s_is64 = (any64 == 0u) ? 1 : 0;
    }
    __syncthreads();
    int is64 = s_is64;
    int e = blockIdx.x * blockDim.x + threadIdx.x;
    if (e < E_EDGES) {
        int src, dst, ty;
        if (is64) {
            const long long* p = (const long long*)ei;
            src = (int)p[e]; dst = (int)p[E_EDGES + e];
            ty = (int)((const long long*)et)[e];
        } else {
            const int* p = (const int*)ei;
            src = p[e]; dst = p[E_EDGES + e];
            ty = ((const int*)et)[e];
        }
        g_src32[e] = src;
        int s = dst * R_REL + ty;
        g_segid[e] = s;
        atomicAdd(&g_hist[s], 1);
    }
    if (e < N_NODES)
        g_batch32[e] = is64 ? (int)((const long long*)bt)[e] : ((const int*)bt)[e];
    if (e < N_NODES * 32) {
        float4 v = ((const float4*)x)[e];
        uint2 o;
        o.x = pk_h2(v.x, v.y);
        o.y = pk_h2(v.z, v.w);
        ((uint2*)xh)[e] = o;
    }
}

__global__ void k_scan1() {
    __shared__ int sd[256];
    int t = threadIdx.x;
    int base = blockIdx.x * 1024 + t * 4;
    int v0 = 0, v1 = 0, v2 = 0, v3 = 0;
    if (base + 0 < NRSEG) v0 = g_hist[base + 0];
    if (base + 1 < NRSEG) v1 = g_hist[base + 1];
    if (base + 2 < NRSEG) v2 = g_hist[base + 2];
    if (base + 3 < NRSEG) v3 = g_hist[base + 3];
    int ts = v0 + v1 + v2 + v3;
    sd[t] = ts; __syncthreads();
    for (int off = 1; off < 256; off <<= 1) {
        int x = (t >= off) ? sd[t - off] : 0;
        __syncthreads();
        sd[t] += x;
        __syncthreads();
    }
    int ex = sd[t] - ts;
    if (base + 0 < NRSEG) g_segstart[base + 0] = ex;
    ex += v0; if (base + 1 < NRSEG) g_segstart[base + 1] = ex;
    ex += v1; if (base + 2 < NRSEG) g_segstart[base + 2] = ex;
    ex += v2; if (base + 3 < NRSEG) g_segstart[base + 3] = ex;
    if (t == 255) g_bsums[blockIdx.x] = sd[255];
}

__global__ void k_scan2(int nb) {
    __shared__ int sd[512];
    int t = threadIdx.x;
    int v = (t < nb) ? g_bsums[t] : 0;
    sd[t] = v; __syncthreads();
    for (int off = 1; off < 512; off <<= 1) {
        int x = (t >= off) ? sd[t - off] : 0;
        __syncthreads();
        sd[t] += x;
        __syncthreads();
    }
    if (t < nb) g_bsums[t] = sd[t] - v;
}

__global__ void k_scan3() {
    int i = blockIdx.x * blockDim.x + threadIdx.x;
    if (i < NRSEG) {
        int v = g_segstart[i] + g_bsums[i >> 10];
        g_segstart[i] = v;
        g_cursor[i] = v;
        int c = g_hist[i];
        g_inv[i] = 1.0f / (float)(c > 0 ? c : 1);
        g_hist[i] = 0;            // self-clear for next graph replay
    }
    if (i < 4 * HID) g_colstats[i] = 0.f;
    if (i == 0) { g_segstart[NRSEG] = E_EDGES; g_sumexp = 0.f; }
}

__global__ void k_permute() {
    int e = blockIdx.x * blockDim.x + threadIdx.x;
    if (e < E_EDGES) {
        int s = g_segid[e];
        int pos = atomicAdd(&g_cursor[s], 1);
        g_srcsorted[pos] = g_src32[e];
    }
}

// ------------------------- aggregation (skip empty, src prefetch) ------------
__global__ void __launch_bounds__(256) k_aggregate(const __half* __restrict__ hsrc) {
    int warp = (blockIdx.x * blockDim.x + threadIdx.x) >> 5;
    int lane = threadIdx.x & 31;
    if (warp >= NRSEG) return;
    int beg = g_segstart[warp], end = g_segstart[warp + 1];
    if (beg == end) return;      // empty segment: aggh row stays zero forever
    float ax = 0.f, ay = 0.f, az = 0.f, aw = 0.f;
    int nxt = g_srcsorted[beg];
    for (int e = beg; e < end; e++) {
        int s = nxt;
        if (e + 1 < end) nxt = g_srcsorted[e + 1];   // prefetch: overlaps gather
        uint2 v = ((const uint2*)(hsrc + (size_t)s * 128))[lane];
        float2 f0 = __half22float2(*(__half2*)&v.x);
        float2 f1 = __half22float2(*(__half2*)&v.y);
        ax += f0.x; ay += f0.y; az += f1.x; aw += f1.y;
    }
    float inv = g_inv[warp];
    uint2 o;
    o.x = pk_h2(ax * inv, ay * inv);
    o.y = pk_h2(az * inv, aw * inv);
    ((uint2*)g_aggh)[(size_t)warp * 32 + lane] = o;
}

// ------------------------- weight prep ---------------------------------------
__global__ void k_wprep(const float* __restrict__ W, const float* __restrict__ root,
                        __half* __restrict__ bh) {
    int idx = blockIdx.x * blockDim.x + threadIdx.x;
    if (idx < 128 * 1152) {
        int c = idx / 1152, k = idx % 1152;
        float v = (k < 1024) ? W[((k >> 7) * 128 + (k & 127)) * 128 + c]
                             : root[(k - 1024) * 128 + c];
        bh[idx] = __float2half_rn(v);
    }
}

template <int K>
__global__ void k_cprep(const float* __restrict__ C, __half* __restrict__ bh,
                        __half* __restrict__ bl) {
    int idx = blockIdx.x * blockDim.x + threadIdx.x;
    if (idx < 128 * K) {
        int c = idx / K, k = idx % K;
        float v = C[k * 128 + c];
        __half h = __float2half_rn(v);
        bh[idx] = h;
        bl[idx] = __float2half_rn(v - __half2float(h));
    }
}

__global__ void k_a1prep(const float* __restrict__ A1) {
    int idx = blockIdx.x * blockDim.x + threadIdx.x;
    if (idx < 64 * 128) {
        int j = idx / 128, k = idx % 128;
        float v = A1[k * 64 + j];
        __half h = __float2half_rn(v);
        g_a1thi[idx] = h;
        g_a1tlo[idx] = __float2half_rn(v - __half2float(h));
    }
}

// ------------------------- mma.sync GEMM (128x128 tile, R15 config) ----------
// 128x128 CTA tile, 256 thr, warp grid 4(M)x2(N), warp tile 32x64.
// MODE 0: +BN stats, out=raw. MODE 1: out=emb fp32 + embh. (1 product, 4-stage)
#define BKC 32
#define ROWB 80          // smem bytes per tile row (32 fp16 + 16B pad)
#define TILE_B 10240     // 128 * 80
#define CP 132           // staging row stride (floats)

template <int MODE, int KT>
__global__ void __launch_bounds__(256, 2) k_mgemm(
    const __half* __restrict__ A, const __half* __restrict__ A2,
    const __half* __restrict__ Bhi,
    const float* __restrict__ bias,
    float* __restrict__ outf, __half* __restrict__ oh,
    float* __restrict__ statsf) {
    constexpr int NCH = KT / BKC;
    constexpr int STAGES = 4;
    constexpr int SBUF = 2 * TILE_B;
    extern __shared__ __align__(16) char dsm[];
    __shared__ float s_bias[128];

    int tid = threadIdx.x;
    int bm = blockIdx.x * 128;
    int wid = tid >> 5, lane = tid & 31;
    int mo = (wid & 3) * 32;
    int no = (wid >> 2) * 64;
    uint32_t sbase = smem_u32(dsm);

    if (tid < 128) s_bias[tid] = bias[tid];

    float acc[2][8][4];
#pragma unroll
    for (int mi = 0; mi < 2; mi++)
#pragma unroll
        for (int j = 0; j < 8; j++)
#pragma unroll
            for (int q = 0; q < 4; q++) acc[mi][j][q] = 0.f;

    auto loadChunk = [&](int i) {
        int st = i % STAGES;
        uint32_t sb = sbase + (uint32_t)(st * SBUF);
        int k0 = i * BKC;
#pragma unroll
        for (int it = 0; it < 2; it++) {
            int idx = it * 256 + tid;
            int row = idx >> 2, seg = idx & 3;
            int n = bm + row;
            bool v = (n < N_NODES);
            int nn = v ? n : 0;
            const __half* pa = (k0 < 1024) ? A + (size_t)nn * 1024 + k0
                                           : A2 + (size_t)nn * 128 + (k0 - 1024);
            cp16(sb + (uint32_t)(row * ROWB + seg * 16), pa + seg * 8, v ? 16u : 0u);
            uint32_t db = sb + TILE_B + (uint32_t)(row * ROWB + seg * 16);
            cp16(db, Bhi + (size_t)row * KT + k0 + seg * 8, 16u);
        }
        cp_commit();
    };

#pragma unroll
    for (int i = 0; i < STAGES - 1 && i < NCH; i++) loadChunk(i);
    for (int i = 0; i < NCH; i++) {
        cp_wait<STAGES - 2>();
        __syncthreads();
        if (i + STAGES - 1 < NCH) loadChunk(i + STAGES - 1);
        else cp_commit();   // empty group: keeps commit-count invariant
        uint32_t ab = sbase + (uint32_t)((i % STAGES) * SBUF);
#pragma unroll
        for (int kk = 0; kk < 2; kk++) {
            uint32_t a[2][4];
#pragma unroll
            for (int mi = 0; mi < 2; mi++) {
                uint32_t r = (uint32_t)(mo + mi * 16 + (lane & 15));
                uint32_t c = (uint32_t)(kk * 16 + (lane >> 4) * 8);
                ldm4(a[mi], ab + r * ROWB + c * 2);
            }
#pragma unroll
            for (int jp = 0; jp < 4; jp++) {
                uint32_t r = (uint32_t)(no + jp * 16 + (lane & 15));
                uint32_t c = (uint32_t)(kk * 16 + (lane >> 4) * 8);
                uint32_t t[4];
                ldm4(t, ab + TILE_B + r * ROWB + c * 2);
                uint32_t bh0[2] = {t[0], t[2]}, bh1[2] = {t[1], t[3]};
#pragma unroll
                for (int mi = 0; mi < 2; mi++) {
                    mma16816(acc[mi][jp * 2 + 0], a[mi], bh0);
                    mma16816(acc[mi][jp * 2 + 1], a[mi], bh1);
                }
            }
        }
    }
    cp_wait<0>();      // drain all (incl. empty) groups before smem reuse
    __syncthreads();

    // ---- stage accumulators to smem (128 x 128) ----
    float* Cs = (float*)dsm;
#pragma unroll
    for (int mi = 0; mi < 2; mi++)
#pragma unroll
        for (int j = 0; j < 8; j++) {
            int r0 = mo + mi * 16 + (lane >> 2);
            int col = no + j * 8 + (lane & 3) * 2;
            *(float2*)&Cs[r0 * CP + col] = make_float2(acc[mi][j][0], acc[mi][j][1]);
            *(float2*)&Cs[(r0 + 8) * CP + col] = make_float2(acc[mi][j][2], acc[mi][j][3]);
        }
    __syncthreads();

    // ---- BN column stats: thread owns (col, half), serial 64-row sum --------
    if (MODE == 0) {
        int col = tid & 127, half = tid >> 7;
        float b = s_bias[col];
        int r0 = half * 64;
        float s = 0.f, q = 0.f;
        int nvalid = N_NODES - bm - r0;
        int rmax = nvalid < 64 ? (nvalid < 0 ? 0 : nvalid) : 64;
        for (int r = 0; r < rmax; r++) {
            float v = Cs[(r0 + r) * CP + col] + b;
            s += v; q += v * v;
        }
        atomicAdd(&statsf[col], s);
        atomicAdd(&statsf[128 + col], q);
    }

    // ---- per-row epilogue: threads 0..127 own row tid ----
    if (tid < 128) {
        int n = bm + tid;
        bool valid = (n < N_NODES);
        const float* crow = &Cs[tid * CP];
        if (valid) {
#pragma unroll
            for (int cb = 0; cb < 4; cb++) {
                float vf[32];
#pragma unroll
                for (int j = 0; j < 32; j++)
                    vf[j] = crow[cb * 32 + j] + s_bias[cb * 32 + j];
#pragma unroll
                for (int j4 = 0; j4 < 8; j4++)
                    *(float4*)&outf[(size_t)n * 128 + cb * 32 + j4 * 4] =
                        make_float4(vf[j4 * 4], vf[j4 * 4 + 1], vf[j4 * 4 + 2], vf[j4 * 4 + 3]);
                if (MODE == 1) {
                    uint32_t* ph = (uint32_t*)(oh + (size_t)n * 128 + cb * 32);
#pragma unroll
                    for (int j2 = 0; j2 < 16; j2++)
                        ph[j2] = pk_h2(vf[j2 * 2], vf[j2 * 2 + 1]);
                }
            }
        }
    }
}

// ------------------------- fused combiner MLP ---------------------------------
// Phase 1: t1 = lrelu([embh|gembh[batch]] @ C1^T + c1)  (K=256, C1 split)
// Phase 2: out = rownorm(t1 @ C2^T + c2)                (K=128, C2 split)
#define T1_OFF 67584                // after Cs staging region (128*132*4)
#define DSMC (T1_OFF + 4 * TILE_B)  // 108544

__global__ void __launch_bounds__(256) k_comb(
    const int* __restrict__ batch,
    const float* __restrict__ c1bias, const float* __restrict__ c2bias,
    float* __restrict__ outf) {
    extern __shared__ __align__(16) char dsm[];
    __shared__ float s_b1[128], s_b2[128];

    int tid = threadIdx.x;
    int bm = blockIdx.x * 128;
    int wid = tid >> 5, lane = tid & 31;
    int mo = (wid & 3) * 32;
    int no = (wid >> 2) * 64;
    uint32_t sbase = smem_u32(dsm);
    float* Cs = (float*)dsm;

    if (tid < 128) { s_b1[tid] = c1bias[tid]; s_b2[tid] = c2bias[tid]; }

    float acc[2][8][4];
#pragma unroll
    for (int mi = 0; mi < 2; mi++)
#pragma unroll
        for (int j = 0; j < 8; j++)
#pragma unroll
            for (int q = 0; q < 4; q++) acc[mi][j][q] = 0.f;

    auto load1 = [&](int i) {
        uint32_t sb = sbase + (uint32_t)((i & 1) * (3 * TILE_B));
        int k0 = i * 32;
#pragma unroll
        for (int it = 0; it < 2; it++) {
            int idx = it * 256 + tid;
            int row = idx >> 2, seg = idx & 3;
            int n = bm + row;
            bool v = (n < N_NODES);
            int nn = v ? n : 0;
            const __half* pa;
            if (k0 < 128) pa = g_embh + (size_t)nn * 128 + k0;
            else {
                int g = v ? batch[nn] : 0;
                pa = g_gembh + (size_t)g * 128 + (k0 - 128);
            }
            cp16(sb + (uint32_t)(row * ROWB + seg * 16), pa + seg * 8, v ? 16u : 0u);
            uint32_t db = sb + TILE_B + (uint32_t)(row * ROWB + seg * 16);
            cp16(db, g_c1hi + (size_t)row * 256 + k0 + seg * 8, 16u);
            cp16(db + TILE_B, g_c1lo + (size_t)row * 256 + k0 + seg * 8, 16u);
        }
        cp_commit();
    };

    load1(0);
    for (int i = 0; i < 8; i++) {
        cp_wait<0>();
        __syncthreads();
        if (i + 1 < 8) load1(i + 1);
        else cp_commit();
        uint32_t ab = sbase + (uint32_t)((i & 1) * (3 * TILE_B));
#pragma unroll
        for (int kk = 0; kk < 2; kk++) {
            uint32_t a[2][4];
#pragma unroll
            for (int mi = 0; mi < 2; mi++) {
                uint32_t r = (uint32_t)(mo + mi * 16 + (lane & 15));
                uint32_t c = (uint32_t)(kk * 16 + (lane >> 4) * 8);
                ldm4(a[mi], ab + r * ROWB + c * 2);
            }
#pragma unroll
            for (int jp = 0; jp < 4; jp++) {
                uint32_t r = (uint32_t)(no + jp * 16 + (lane & 15));
                uint32_t c = (uint32_t)(kk * 16 + (lane >> 4) * 8);
                uint32_t bd = ab + TILE_B + r * ROWB + c * 2;
                uint32_t t[4], u[4];
                ldm4(t, bd);
                ldm4(u, bd + TILE_B);
                uint32_t bh0[2] = {t[0], t[2]}, bh1[2] = {t[1], t[3]};
                uint32_t bl0[2] = {u[0], u[2]}, bl1[2] = {u[1], u[3]};
#pragma unroll
                for (int mi = 0; mi < 2; mi++) {
                    mma16816(acc[mi][jp * 2 + 0], a[mi], bh0);
                    mma16816(acc[mi][jp * 2 + 0], a[mi], bl0);
                    mma16816(acc[mi][jp * 2 + 1], a[mi], bh1);
                    mma16816(acc[mi][jp * 2 + 1], a[mi], bl1);
                }
            }
        }
    }
    cp_wait<0>();
    __syncthreads();

#pragma unroll
    for (int mi = 0; mi < 2; mi++)
#pragma unroll
        for (int j = 0; j < 8; j++) {
            int r0 = mo + mi * 16 + (lane >> 2);
            int col = no + j * 8 + (lane & 3) * 2;
            *(float2*)&Cs[r0 * CP + col] = make_float2(acc[mi][j][0], acc[mi][j][1]);
            *(float2*)&Cs[(r0 + 8) * CP + col] = make_float2(acc[mi][j][2], acc[mi][j][3]);
        }
    __syncthreads();

    if (tid < 128) {
        const float* crow = &Cs[tid * CP];
#pragma unroll
        for (int cb = 0; cb < 4; cb++) {
            uint32_t* pt = (uint32_t*)(dsm + T1_OFF + cb * TILE_B + tid * ROWB);
#pragma unroll
            for (int j2 = 0; j2 < 16; j2++) {
                float v0 = lrelu(crow[cb * 32 + j2 * 2 + 0] + s_b1[cb * 32 + j2 * 2 + 0]);
                float v1 = lrelu(crow[cb * 32 + j2 * 2 + 1] + s_b1[cb * 32 + j2 * 2 + 1]);
                pt[j2] = pk_h2(v0, v1);
            }
        }
    }
    __syncthreads();

#pragma unroll
    for (int mi = 0; mi < 2; mi++)
#pragma unroll
        for (int j = 0; j < 8; j++)
#pragma unroll
            for (int q = 0; q < 4; q++) acc[mi][j][q] = 0.f;

    auto load2 = [&](int i) {
        uint32_t sb = sbase + (uint32_t)((i & 1) * (2 * TILE_B));
        int k0 = i * 32;
#pragma unroll
        for (int it = 0; it < 2; it++) {
            int idx = it * 256 + tid;
            int row = idx >> 2, seg = idx & 3;
            cp16(sb + (uint32_t)(row * ROWB + seg * 16),
                 g_c2hi + (size_t)row * 128 + k0 + seg * 8, 16u);
            cp16(sb + TILE_B + (uint32_t)(row * ROWB + seg * 16),
                 g_c2lo + (size_t)row * 128 + k0 + seg * 8, 16u);
        }
        cp_commit();
    };

    load2(0);
    for (int i = 0; i < 4; i++) {
        cp_wait<0>();
        __syncthreads();
        if (i + 1 < 4) load2(i + 1);
        else cp_commit();
        uint32_t ab = sbase + (uint32_t)((i & 1) * (2 * TILE_B));
        uint32_t at = sbase + (uint32_t)(T1_OFF + i * TILE_B);
#pragma unroll
        for (int kk = 0; kk < 2; kk++) {
            uint32_t a[2][4];
#pragma unroll
            for (int mi = 0; mi < 2; mi++) {
                uint32_t r = (uint32_t)(mo + mi * 16 + (lane & 15));
                uint32_t c = (uint32_t)(kk * 16 + (lane >> 4) * 8);
                ldm4(a[mi], at + r * ROWB + c * 2);
            }
#pragma unroll
            for (int jp = 0; jp < 4; jp++) {
                uint32_t r = (uint32_t)(no + jp * 16 + (lane & 15));
                uint32_t c = (uint32_t)(kk * 16 + (lane >> 4) * 8);
                uint32_t bd = ab + r * ROWB + c * 2;
                uint32_t t[4], u[4];
                ldm4(t, bd);
                ldm4(u, bd + TILE_B);
                uint32_t bh0[2] = {t[0], t[2]}, bh1[2] = {t[1], t[3]};
                uint32_t bl0[2] = {u[0], u[2]}, bl1[2] = {u[1], u[3]};
#pragma unroll
                for (int mi = 0; mi < 2; mi++) {
                    mma16816(acc[mi][jp * 2 + 0], a[mi], bh0);
                    mma16816(acc[mi][jp * 2 + 0], a[mi], bl0);
                    mma16816(acc[mi][jp * 2 + 1], a[mi], bh1);
                    mma16816(acc[mi][jp * 2 + 1], a[mi], bl1);
                }
            }
        }
    }
    cp_wait<0>();
    __syncthreads();

#pragma unroll
    for (int mi = 0; mi < 2; mi++)
#pragma unroll
        for (int j = 0; j < 8; j++) {
            int r0 = mo + mi * 16 + (lane >> 2);
            int col = no + j * 8 + (lane & 3) * 2;
            *(float2*)&Cs[r0 * CP + col] = make_float2(acc[mi][j][0], acc[mi][j][1]);
            *(float2*)&Cs[(r0 + 8) * CP + col] = make_float2(acc[mi][j][2], acc[mi][j][3]);
        }
    __syncthreads();

    if (tid < 128) {
        int n = bm + tid;
        bool valid = (n < N_NODES);
        const float* crow = &Cs[tid * CP];
        float ss = 0.f;
#pragma unroll 8
        for (int c = 0; c < 128; c++) {
            float v = crow[c] + s_b2[c];
            ss += v * v;
        }
        float sc = 1.f / fmaxf(sqrtf(ss), 1e-12f);
        if (valid) {
#pragma unroll
            for (int c4 = 0; c4 < 32; c4++) {
                float4 o;
                o.x = (crow[c4 * 4 + 0] + s_b2[c4 * 4 + 0]) * sc;
                o.y = (crow[c4 * 4 + 1] + s_b2[c4 * 4 + 1]) * sc;
                o.z = (crow[c4 * 4 + 2] + s_b2[c4 * 4 + 2]) * sc;
                o.w = (crow[c4 * 4 + 3] + s_b2[c4 * 4 + 3]) * sc;
                *(float4*)&outf[(size_t)n * 128 + c4 * 4] = o;
            }
        }
    }
}

// ------------------------- BN apply (self-computing scale/shift) --------------
__global__ void k_bnapply(const float* __restrict__ gamma, const float* __restrict__ beta,
                          const float* __restrict__ stats) {
    __shared__ float s_sc[128], s_sh[128];
    if (threadIdx.x < 128) {
        int c = threadIdx.x;
        float inv_n = 1.f / (float)N_NODES;
        float mu = stats[c] * inv_n;
        float var = fmaxf(stats[128 + c] * inv_n - mu * mu, 0.f);
        float sc = gamma[c] * rsqrtf(var + EPS_BN);
        s_sc[c] = sc;
        s_sh[c] = beta[c] - mu * sc;
    }
    __syncthreads();
    int i = blockIdx.x * blockDim.x + threadIdx.x;
    if (i < N_NODES * 32) {
        float4 v = ((const float4*)g_raw)[i];
        int c4 = i & 31;
        float4 sc = *(const float4*)&s_sc[c4 * 4];
        float4 sh = *(const float4*)&s_sh[c4 * 4];
        float ox = lrelu(v.x * sc.x + sh.x);
        float oy = lrelu(v.y * sc.y + sh.y);
        float oz = lrelu(v.z * sc.z + sh.z);
        float ow = lrelu(v.w * sc.w + sh.w);
        uint2 o;
        o.x = pk_h2(ox, oy);
        o.y = pk_h2(oz, ow);
        ((uint2*)g_hh)[i] = o;
    }
}

// ------------------------- attention scores (tensor cores + fused sumexp) -----
#define SROWB 272
#define SAT 34816
#define SBT 17408
#define SCP 68

__global__ void __launch_bounds__(256, 2) k_scoresT(
    const float* __restrict__ a1, const float* __restrict__ A2v,
    const float* __restrict__ a2v) {
    extern __shared__ __align__(16) char dsm[];
    __shared__ float s_a1[64];
    __shared__ float s_A2[64];
    __shared__ float s_esum;
    int tid = threadIdx.x;
    int bm = blockIdx.x * 128;
    int wid = tid >> 5, lane = tid & 31;
    int mo = (wid & 3) * 32;
    int no = (wid >> 2) * 32;
    uint32_t sbase = smem_u32(dsm);

    if (tid < 64) { s_a1[tid] = a1[tid]; s_A2[tid] = A2v[tid]; }
    if (tid == 0) s_esum = 0.f;

#pragma unroll
    for (int it = 0; it < 8; it++) {
        int idx = it * 256 + tid;
        int row = idx >> 4, seg = idx & 15;
        int n = bm + row;
        bool v = (n < N_NODES);
        cp16(sbase + (uint32_t)(row * SROWB + seg * 16),
             g_embh + (size_t)(v ? n : 0) * 128 + seg * 8, v ? 16u : 0u);
    }
#pragma unroll
    for (int it = 0; it < 4; it++) {
        int idx = it * 256 + tid;
        int row = idx >> 4, seg = idx & 15;
        uint32_t db = sbase + SAT + (uint32_t)(row * SROWB + seg * 16);
        cp16(db, g_a1thi + (size_t)row * 128 + seg * 8, 16u);
        cp16(db + SBT, g_a1tlo + (size_t)row * 128 + seg * 8, 16u);
    }
    cp_commit();
    cp_wait<0>();
    __syncthreads();

    float acc[2][4][4];
#pragma unroll
    for (int mi = 0; mi < 2; mi++)
#pragma unroll
        for (int j = 0; j < 4; j++)
#pragma unroll
            for (int q = 0; q < 4; q++) acc[mi][j][q] = 0.f;

#pragma unroll
    for (int kk = 0; kk < 8; kk++) {
        uint32_t a[2][4];
#pragma unroll
        for (int mi = 0; mi < 2; mi++) {
            uint32_t r = (uint32_t)(mo + mi * 16 + (lane & 15));
            uint32_t c = (uint32_t)(kk * 16 + (lane >> 4) * 8);
            ldm4(a[mi], sbase + r * SROWB + c * 2);
        }
#pragma unroll
        for (int jn = 0; jn < 2; jn++) {
            uint32_t r = (uint32_t)(no + jn * 16 + (lane & 15));
            uint32_t c = (uint32_t)(kk * 16 + (lane >> 4) * 8);
            uint32_t bd = sbase + SAT + r * SROWB + c * 2;
            uint32_t t[4], u[4];
            ldm4(t, bd);
            ldm4(u, bd + SBT);
            uint32_t bh0[2] = {t[0], t[2]}, bh1[2] = {t[1], t[3]};
            uint32_t bl0[2] = {u[0], u[2]}, bl1[2] = {u[1], u[3]};
#pragma unroll
            for (int mi = 0; mi < 2; mi++) {
                mma16816(acc[mi][jn * 2 + 0], a[mi], bh0);
                mma16816(acc[mi][jn * 2 + 0], a[mi], bl0);
                mma16816(acc[mi][jn * 2 + 1], a[mi], bh1);
                mma16816(acc[mi][jn * 2 + 1], a[mi], bl1);
            }
        }
    }
    __syncthreads();

    float* Cs = (float*)dsm;
#pragma unroll
    for (int mi = 0; mi < 2; mi++)
#pragma unroll
        for (int j = 0; j < 4; j++) {
            int r0 = mo + mi * 16 + (lane >> 2);
            int col = no + j * 8 + (lane & 3) * 2;
            *(float2*)&Cs[r0 * SCP + col] = make_float2(acc[mi][j][0], acc[mi][j][1]);
            *(float2*)&Cs[(r0 + 8) * SCP + col] = make_float2(acc[mi][j][2], acc[mi][j][3]);
        }
    __syncthreads();

    if (tid < 128) {
        int n = bm + tid;
        bool valid = (n < N_NODES);
        const float* crow = &Cs[tid * SCP];
        float s = 0.f;
#pragma unroll 8
        for (int j = 0; j < 64; j++)
            s += lrelu(crow[j] + s_a1[j]) * s_A2[j];
        float score = s + a2v[0];
        if (valid) g_scores[n] = score;
        float ex = valid ? expf(score) : 0.f;
#pragma unroll
        for (int off = 16; off > 0; off >>= 1)
            ex += __shfl_xor_sync(0xffffffffu, ex, off);
        if ((tid & 31) == 0) atomicAdd(&s_esum, ex);
    }
    __syncthreads();
    if (tid == 0) atomicAdd(&g_sumexp, s_esum);
}

__global__ void k_gbounds() {
    int i = blockIdx.x * blockDim.x + threadIdx.x;
    if (i <= N_NODES) {
        int cur = (i < N_NODES) ? g_batch32[i] : NG;
        int prev = (i == 0) ? -1 : g_batch32[i - 1];
        for (int g = prev + 1; g <= cur && g <= NG; g++) g_gstart[g] = i;
    }
}

// pool: 1024 thr = 32 node-lanes x 32 col-threads
__global__ void __launch_bounds__(1024) k_pool() {
    __shared__ float s_red[32][128];
    int g = blockIdx.x;
    int ty = threadIdx.x >> 5, tx = threadIdx.x & 31;
    float invs = 1.f / g_sumexp;
    int b = g_gstart[g], e = g_gstart[g + 1];
    float4 acc = make_float4(0.f, 0.f, 0.f, 0.f);
    for (int n = b + ty; n < e; n += 32) {
        float w = expf(g_scores[n]) * invs;
        float4 v = *(const float4*)&g_emb[(size_t)n * 128 + tx * 4];
        acc.x += v.x * w; acc.y += v.y * w; acc.z += v.z * w; acc.w += v.w * w;
    }
    *(float4*)&s_red[ty][tx * 4] = acc;
    __syncthreads();
    if (threadIdx.x < 128) {
        int c = threadIdx.x;
        float s = 0.f;
#pragma unroll
        for (int t = 0; t < 32; t++) s += s_red[t][c];
        g_gembh[g * 128 + c] = __float2half_rn(s);
    }
}

// ------------------------- host launcher --------------------------------------
extern "C" void kernel_launch(void* const* d_in, const int* in_sizes, int n_in,
                              void* d_out, int out_size) {
    const float* x     = (const float*)d_in[0];
    const void*  ei    = d_in[1];
    const void*  et    = d_in[2];
    const void*  bt    = d_in[3];
    const float* W1    = (const float*)d_in[4];
    const float* root1 = (const float*)d_in[5];
    const float* b1    = (const float*)d_in[6];
    const float* W2    = (const float*)d_in[7];
    const float* root2 = (const float*)d_in[8];
    const float* b2    = (const float*)d_in[9];
    const float* W3    = (const float*)d_in[10];
    const float* root3 = (const float*)d_in[11];
    const float* b3    = (const float*)d_in[12];
    const float* g1    = (const float*)d_in[13];
    const float* beta1 = (const float*)d_in[14];
    const float* g2    = (const float*)d_in[15];
    const float* beta2 = (const float*)d_in[16];
    const float* A1    = (const float*)d_in[17];
    const float* a1    = (const float*)d_in[18];
    const float* A2    = (const float*)d_in[19];
    const float* a2    = (const float*)d_in[20];
    const float* C1    = (const float*)d_in[21];
    const float* c1    = (const float*)d_in[22];
    const float* C2    = (const float*)d_in[23];
    const float* c2    = (const float*)d_in[24];
    float* out = (float*)d_out;

    void* p;
    cudaGetSymbolAddress(&p, g_aggh);   __half* aggh = (__half*)p;
    cudaGetSymbolAddress(&p, g_raw);    float* raw  = (float*)p;
    cudaGetSymbolAddress(&p, g_emb);    float* emb  = (float*)p;
    cudaGetSymbolAddress(&p, g_xh);     __half* xh = (__half*)p;
    cudaGetSymbolAddress(&p, g_hh);     __half* hh = (__half*)p;
    cudaGetSymbolAddress(&p, g_embh);   __half* embh = (__half*)p;
    cudaGetSymbolAddress(&p, g_w1hi);   __half* w1hi = (__half*)p;
    cudaGetSymbolAddress(&p, g_w2hi);   __half* w2hi = (__half*)p;
    cudaGetSymbolAddress(&p, g_w3hi);   __half* w3hi = (__half*)p;
    cudaGetSymbolAddress(&p, g_c1hi);   __half* c1hi = (__half*)p;
    cudaGetSymbolAddress(&p, g_c1lo);   __half* c1lo = (__half*)p;
    cudaGetSymbolAddress(&p, g_c2hi);   __half* c2hi = (__half*)p;
    cudaGetSymbolAddress(&p, g_c2lo);   __half* c2lo = (__half*)p;
    cudaGetSymbolAddress(&p, g_batch32); int* batch32 = (int*)p;
    cudaGetSymbolAddress(&p, g_colstats); float* colstats = (float*)p;

    const int DSM0 = 4 * 2 * TILE_B;            // 81920 (layer GEMMs, R15 config)
    const int DSMS = SAT + 2 * SBT;             // 69632 (scores)
    cudaFuncSetAttribute(k_mgemm<0, 1152>, cudaFuncAttributeMaxDynamicSharedMemorySize, DSM0);
    cudaFuncSetAttribute(k_mgemm<1, 1152>, cudaFuncAttributeMaxDynamicSharedMemorySize, DSM0);
    cudaFuncSetAttribute(k_comb, cudaFuncAttributeMaxDynamicSharedMemorySize, DSMC);
    cudaFuncSetAttribute(k_scoresT, cudaFuncAttributeMaxDynamicSharedMemorySize, DSMS);

    const int NB1 = (NRSEG + 1023) / 1024;
    const int GB128 = (N_NODES + 127) / 128;  // 391
    const int AGG_BLOCKS = NRSEG / 8;         // 50000

    // prep chain
    k_edge_prep<<<(N_NODES * 32 + 255) / 256, 256>>>(ei, et, bt, x, xh);
    k_scan1<<<NB1, 256>>>();
    k_scan2<<<1, 512>>>(NB1);
    k_scan3<<<(NRSEG + 255) / 256, 256>>>();
    k_permute<<<(E_EDGES + 255) / 256, 256>>>();
    k_aggregate<<<AGG_BLOCKS, 256>>>(xh);

    k_wprep<<<(128 * 1152 + 255) / 256, 256>>>(W1, root1, w1hi);
    k_wprep<<<(128 * 1152 + 255) / 256, 256>>>(W2, root2, w2hi);
    k_wprep<<<(128 * 1152 + 255) / 256, 256>>>(W3, root3, w3hi);
    k_cprep<256><<<(128 * 256 + 255) / 256, 256>>>(C1, c1hi, c1lo);
    k_cprep<128><<<(128 * 128 + 255) / 256, 256>>>(C2, c2hi, c2lo);
    k_a1prep<<<(64 * 128 + 255) / 256, 256>>>(A1);
    k_gbounds<<<(N_NODES + 256) / 256, 256>>>();

    // layer 1 (stats -> colstats[0:256))
    k_mgemm<0, 1152><<<GB128, 256, DSM0>>>(aggh, xh, w1hi, b1, raw, nullptr, colstats);
    k_bnapply<<<(N_NODES * 32 + 255) / 256, 256>>>(g1, beta1, colstats);

    // layer 2 (stats -> colstats[256:512))
    k_aggregate<<<AGG_BLOCKS, 256>>>(hh);
    k_mgemm<0, 1152><<<GB128, 256, DSM0>>>(aggh, hh, w2hi, b2, raw, nullptr, colstats + 256);
    k_bnapply<<<(N_NODES * 32 + 255) / 256, 256>>>(g2, beta2, colstats + 256);

    // layer 3
    k_aggregate<<<AGG_BLOCKS, 256>>>(hh);
    k_mgemm<1, 1152><<<GB128, 256, DSM0>>>(aggh, hh, w3hi, b3, emb, embh, nullptr);

    // attention pooling (sumexp fused into scores; softmax max-shift cancels)
    k_scoresT<<<GB128, 256, DSMS>>>(a1, A2, a2);
    k_pool<<<NG, 1024>>>();

    // fused combiner MLP + row normalize
    k_comb<<<GB128, 256, DSMC>>>(batch32, c1, c2, out);

    (void)in_sizes; (void)n_in; (void)out_size;
}